// round 9
// baseline (speedup 1.0000x reference)
#include <cuda_runtime.h>
#include <cuda_bf16.h>
#include <cstdint>

#define B_      16384
#define D_      256
#define NSTEPS_ 5
#define BD      (B_*D_)

// ---------------------------------------------------------------------------
// Persistent state (re-initialized on every kernel_launch -> deterministic).
__device__ __align__(16) float g_x  [BD];
__device__ __align__(16) float g_xa [BD];
__device__ __align__(16) float g_vx [BD];
__device__ __align__(16) float g_xd [BD];
__device__ __align__(16) float g_vxd[BD];
__device__ __align__(16) float g_p  [BD];
__device__ __align__(16) __nv_bfloat16 g_xbf [BD];   // exact bf16 mirror of g_x
__device__ __align__(16) __nv_bfloat16 g_xdbf[BD];   // exact bf16 mirror of g_xd
// W 3-level bf16 split, TRANSPOSED: g_Wt[level][n][k], n,k in [0,256).
__device__ __align__(16) __nv_bfloat16 g_Wt[3 * 256 * 256];

// ---------------------------------------------------------------------------
__device__ __forceinline__ void cpasync16(uint32_t dst, const void* src) {
    asm volatile("cp.async.ca.shared.global [%0], [%1], 16;" :: "r"(dst), "l"(src));
}

__device__ __forceinline__ float flip_p(float vx, float bv, float ga, float s) {
    float d  = ((vx + bv) * s) * 0.5f;
    float gm = d - (ga * 0.5f) * s;
    float t  = gm - 2.5f;
    return 1.0f / (1.0f + expf(-t));
}

__global__ void kinit(const float* __restrict__ x_in, const float* __restrict__ xa_in) {
    int i = blockIdx.x * blockDim.x + threadIdx.x;
    if (i < BD) {
        float x = x_in[i];
        g_x[i] = x; g_xa[i] = xa_in[i];
        g_xbf[i] = __float2bfloat16(x);          // exact (binary)
    }
}

// W staging: 3-level bf16 Kahan split, stored transposed [level][n][k].
// v[n] = sum_k z[k] * W[k][n];  W row-major index k*256+n.
__global__ void kprep(const float* __restrict__ Wm_in) {
    int k = threadIdx.x;
    int n = blockIdx.x;
    float w = Wm_in[k * 256 + n];
    __nv_bfloat16 h = __float2bfloat16(w);
    float r1 = w - __bfloat162float(h);
    __nv_bfloat16 m = __float2bfloat16(r1);
    float r2 = r1 - __bfloat162float(m);
    __nv_bfloat16 l = __float2bfloat16(r2);
    size_t base = (size_t)n * 256 + k;
    g_Wt[base]             = h;
    g_Wt[65536 + base]     = m;
    g_Wt[2 * 65536 + base] = l;
}

// ---------------------------------------------------------------------------
// Tensor-core GEMM via mma.sync (baseline PTX, works on compute_103):
// C[16384,256] = A @ (Wh+Wm+Wl).  CTA: M128 x N64, 8 warps (warp = M16 x N64).
// K double-buffered in 32-chunks via cp.async. All 3 levels accumulate into
// the same f32 fragments (order: per k16-tile, levels h,m,l — fixed, deterministic).
#define KC 32
__global__ __launch_bounds__(256) void gemm_tc(const __nv_bfloat16* __restrict__ Abf,
                                               float* __restrict__ C) {
    __shared__ __align__(16) __nv_bfloat16 Asm[2][128 * KC];
    __shared__ __align__(16) __nv_bfloat16 Wsm[2][3][64 * KC];

    const int t    = threadIdx.x;
    const int wid  = t >> 5;
    const int lane = t & 31;
    const int g    = lane >> 2;     // row group 0..7
    const int tg   = lane & 3;      // col pair 0..3
    const int m0   = blockIdx.x * 128;
    const int n0   = blockIdx.y * 64;

    float acc[8][4];
    #pragma unroll
    for (int nt = 0; nt < 8; nt++)
        #pragma unroll
        for (int r = 0; r < 4; r++) acc[nt][r] = 0.0f;

    auto ldchunk = [&](int c, int buf) {
        int k0 = c * KC;
        #pragma unroll
        for (int i = 0; i < 2; i++) {                 // A: 128x32 bf16, 512 x 16B
            int u = t + 256 * i;
            int m = u >> 2, koff = (u & 3) * 8;
            uint32_t dst = (uint32_t)__cvta_generic_to_shared(&Asm[buf][m * KC + koff]);
            cpasync16(dst, &Abf[(size_t)(m0 + m) * 256 + k0 + koff]);
        }
        #pragma unroll
        for (int i = 0; i < 3; i++) {                 // W: 3 x 64x32 bf16, 768 x 16B
            int u = t + 256 * i;
            int l = u >> 8, rem = u & 255;
            int n = rem >> 2, koff = (rem & 3) * 8;
            uint32_t dst = (uint32_t)__cvta_generic_to_shared(&Wsm[buf][l][n * KC + koff]);
            cpasync16(dst, &g_Wt[(size_t)l * 65536 + (size_t)(n0 + n) * 256 + k0 + koff]);
        }
        asm volatile("cp.async.commit_group;");
    };

    ldchunk(0, 0);

    #pragma unroll 1
    for (int c = 0; c < 256 / KC; c++) {
        if (c + 1 < 256 / KC) {
            ldchunk(c + 1, (c + 1) & 1);
            asm volatile("cp.async.wait_group 1;");
        } else {
            asm volatile("cp.async.wait_group 0;");
        }
        __syncthreads();

        const int buf = c & 1;
        const uint16_t* Ab = (const uint16_t*)&Asm[buf][0];

        #pragma unroll
        for (int kt = 0; kt < 2; kt++) {
            int kb = kt * 16 + tg * 2;
            uint32_t a0 = *(const uint32_t*)&Ab[(wid * 16 + g)     * KC + kb];
            uint32_t a1 = *(const uint32_t*)&Ab[(wid * 16 + g + 8) * KC + kb];
            uint32_t a2 = *(const uint32_t*)&Ab[(wid * 16 + g)     * KC + kb + 8];
            uint32_t a3 = *(const uint32_t*)&Ab[(wid * 16 + g + 8) * KC + kb + 8];
            #pragma unroll
            for (int l = 0; l < 3; l++) {
                const uint16_t* Wb = (const uint16_t*)&Wsm[buf][l][0];
                #pragma unroll
                for (int nt = 0; nt < 8; nt++) {
                    uint32_t b0 = *(const uint32_t*)&Wb[(nt * 8 + g) * KC + kb];
                    uint32_t b1 = *(const uint32_t*)&Wb[(nt * 8 + g) * KC + kb + 8];
                    asm volatile(
                        "mma.sync.aligned.m16n8k16.row.col.f32.bf16.bf16.f32 "
                        "{%0,%1,%2,%3}, {%4,%5,%6,%7}, {%8,%9}, {%0,%1,%2,%3};"
                        : "+f"(acc[nt][0]), "+f"(acc[nt][1]),
                          "+f"(acc[nt][2]), "+f"(acc[nt][3])
                        : "r"(a0), "r"(a1), "r"(a2), "r"(a3), "r"(b0), "r"(b1));
                }
            }
        }
        __syncthreads();
    }

    // Epilogue: c0,c1 -> row g, cols 2tg,2tg+1; c2,c3 -> row g+8.
    #pragma unroll
    for (int nt = 0; nt < 8; nt++) {
        size_t row = (size_t)(m0 + wid * 16 + g);
        int    col = n0 + nt * 8 + tg * 2;
        float2 lo = make_float2(acc[nt][0], acc[nt][1]);
        float2 hi = make_float2(acc[nt][2], acc[nt][3]);
        *(float2*)&C[row * 256 + col]       = lo;
        *(float2*)&C[(row + 8) * 256 + col] = hi;
    }
}

// ---------------------------------------------------------------------------
__global__ void phase1(const float* __restrict__ rr_s, const float* __restrict__ bvec) {
    int i = blockIdx.x * blockDim.x + threadIdx.x;
    if (i >= BD) return;
    float x  = g_x[i];
    float s  = 1.0f - 2.0f * x;
    float ga = (x - g_xa[i]) / 1.0e4f;
    float p  = flip_p(g_vx[i], bvec[i & 255], ga, s);
    float ind = (rr_s[i] < p) ? 1.0f : 0.0f;
    float xd = x + ind * s;
    g_xd[i]   = xd;
    g_xdbf[i] = __float2bfloat16(xd);
    g_p[i]    = p;
}

__device__ __forceinline__ double wsumd(double v) {
    #pragma unroll
    for (int off = 16; off; off >>= 1) v += __shfl_xor_sync(0xffffffffu, v, off, 32);
    return v;
}

__global__ __launch_bounds__(256) void phase2(const float* __restrict__ noise_s,
                                              const float* __restrict__ u_s,
                                              const float* __restrict__ rr_next,
                                              const float* __restrict__ bvec,
                                              float* __restrict__ out, int last) {
    int gwarp = (blockIdx.x * blockDim.x + threadIdx.x) >> 5;
    int lane  = threadIdx.x & 31;
    if (gwarp >= B_) return;
    size_t base  = (size_t)gwarp * 256 + lane * 8;
    int    dbase = lane * 8;

    float xv[8], xav[8], vxv[8], vxdv[8], xdv[8], pv[8], nzv[8], bvv[8];
    #pragma unroll
    for (int h = 0; h < 2; h++) {
        *(float4*)&xv  [4*h] = __ldg((const float4*)&g_x  [base + 4*h]);
        *(float4*)&xav [4*h] = __ldg((const float4*)&g_xa [base + 4*h]);
        *(float4*)&vxv [4*h] = __ldg((const float4*)&g_vx [base + 4*h]);
        *(float4*)&vxdv[4*h] = __ldg((const float4*)&g_vxd[base + 4*h]);
        *(float4*)&xdv [4*h] = __ldg((const float4*)&g_xd [base + 4*h]);
        *(float4*)&pv  [4*h] = __ldg((const float4*)&g_p  [base + 4*h]);
        *(float4*)&nzv [4*h] = __ldg((const float4*)&noise_s[base + 4*h]);
        *(float4*)&bvv [4*h] = __ldg((const float4*)&bvec [dbase + 4*h]);
    }

    float xdav[8], p2v[8];
    double q = 0.0;

    #pragma unroll
    for (int j = 0; j < 8; j++) {
        float x = xv[j], xa = xav[j], vx = vxv[j], vxd = vxdv[j];
        float xd = xdv[j], p = pv[j], nz = nzv[j], bv = bvv[j];

        float ga  = (x - xa) / 1.0e4f;
        float ind = (x != xd) ? 1.0f : 0.0f;
        float xda = (xa + 0.25f * ga) + 0.70710678118654752f * nz;

        float s2  = 1.0f - 2.0f * xd;
        float ga2 = (xd - xda) / 1.0e4f;
        float p2  = flip_p(vxd, bv, ga2, s2);

        float a1 = (ind != 0.0f) ? (p  + 1e-10f) : ((1.0f - p)  + 1e-10f);
        float a2 = (ind != 0.0f) ? (p2 + 1e-10f) : ((1.0f - p2) + 1e-10f);
        float t_log = __logf(a2) - __logf(a1);

        float dc = x  - xa;
        float dn = xd - xda;
        float t_m = ((0.5f * (vxd * xd) + bv * xd) - (dn * dn) * 5e-5f)
                  - ((0.5f * (vx  * x ) + bv * x ) - (dc * dc) * 5e-5f);

        float ff = xda - (xa + 0.25f * ga);
        float fr = xa  - (xda + 0.25f * ga2);
        float t_q = ff * ff - fr * fr;

        q += (double)(t_log + t_m + t_q);

        xdav[j] = xda; p2v[j] = p2;
    }

    double la = wsumd(q);
    int accept = la > log((double)__ldg(&u_s[gwarp]));

    if (last) {
        float o1[8], o2[8];
        #pragma unroll
        for (int j = 0; j < 8; j++) {
            o1[j] = accept ? xdv[j]  : xv[j];
            o2[j] = accept ? xdav[j] : xav[j];
        }
        #pragma unroll
        for (int h = 0; h < 2; h++) {
            *(float4*)&out[base + 4*h]      = *(float4*)&o1[4*h];
            *(float4*)&out[BD + base + 4*h] = *(float4*)&o2[4*h];
        }
        return;
    }

    if (accept) {
        #pragma unroll
        for (int h = 0; h < 2; h++) {
            *(float4*)&g_x [base + 4*h] = *(float4*)&xdv [4*h];
            *(float4*)&g_xa[base + 4*h] = *(float4*)&xdav[4*h];
            *(float4*)&g_vx[base + 4*h] = *(float4*)&vxdv[4*h];
            *(float4*)&g_p [base + 4*h] = *(float4*)&p2v [4*h];
        }
    }

    // Next proposal: p_next = accept ? p2 : p (bit-identical to recompute).
    float rrv[8], xdn[8];
    __nv_bfloat16 xdb[8];
    #pragma unroll
    for (int h = 0; h < 2; h++)
        *(float4*)&rrv[4*h] = __ldg((const float4*)&rr_next[base + 4*h]);
    #pragma unroll
    for (int j = 0; j < 8; j++) {
        float xn = accept ? xdv[j] : xv[j];
        float pn = accept ? p2v[j] : pv[j];
        float s  = 1.0f - 2.0f * xn;
        float ind = (rrv[j] < pn) ? 1.0f : 0.0f;
        xdn[j] = xn + ind * s;
        xdb[j] = __float2bfloat16(xdn[j]);
    }
    #pragma unroll
    for (int h = 0; h < 2; h++)
        *(float4*)&g_xd[base + 4*h] = *(float4*)&xdn[4*h];
    *(uint4*)&g_xdbf[base] = *(uint4*)&xdb[0];
}

// ---------------------------------------------------------------------------
extern "C" void kernel_launch(void* const* d_in, const int* in_sizes, int n_in,
                              void* d_out, int out_size) {
    (void)in_sizes; (void)n_in; (void)out_size;
    const float* x_in  = (const float*)d_in[0];
    const float* xa_in = (const float*)d_in[1];
    const float* Wm    = (const float*)d_in[2];
    const float* bvec  = (const float*)d_in[3];
    const float* rr    = (const float*)d_in[4];
    const float* noise = (const float*)d_in[5];
    const float* u     = (const float*)d_in[6];
    float* out = (float*)d_out;

    __nv_bfloat16* xbf_p;  cudaGetSymbolAddress((void**)&xbf_p,  g_xbf);
    __nv_bfloat16* xdbf_p; cudaGetSymbolAddress((void**)&xdbf_p, g_xdbf);
    float* vx_p;  cudaGetSymbolAddress((void**)&vx_p,  g_vx);
    float* vxd_p; cudaGetSymbolAddress((void**)&vxd_p, g_vxd);

    dim3 ggrid(B_ / 128, 2);                 // 128 M-blocks x (256/64=4)... see below
    ggrid = dim3(B_ / 128, 256 / 64);

    kinit<<<BD / 256, 256>>>(x_in, xa_in);
    kprep<<<256, 256>>>(Wm);
    gemm_tc<<<ggrid, 256>>>(xbf_p, vx_p);                // g_vx = x @ W
    phase1<<<BD / 256, 256>>>(rr, bvec);                 // proposal for step 0
    for (int s = 0; s < NSTEPS_; s++) {
        gemm_tc<<<ggrid, 256>>>(xdbf_p, vxd_p);          // g_vxd = x_delta @ W
        int lastf = (s == NSTEPS_ - 1);
        phase2<<<B_ / 8, 256>>>(noise + (size_t)s * BD, u + (size_t)s * B_,
                                lastf ? (const float*)d_in[4]
                                      : rr + (size_t)(s + 1) * BD,
                                bvec, out, lastf);
    }
}

// round 10
// speedup vs baseline: 1.4334x; 1.4334x over previous
#include <cuda_runtime.h>
#include <cuda_bf16.h>
#include <cstdint>

#define B_      16384
#define D_      256
#define NSTEPS_ 5
#define BD      (B_*D_)

// ---------------------------------------------------------------------------
// Persistent state (re-initialized on every kernel_launch -> deterministic).
__device__ __align__(16) float g_x  [BD];
__device__ __align__(16) float g_xa [BD];
__device__ __align__(16) float g_vx [BD];
__device__ __align__(16) float g_xd [BD];
__device__ __align__(16) float g_vxd[BD];
__device__ __align__(16) float g_p  [BD];
__device__ __align__(16) __nv_bfloat16 g_xbf [BD];   // exact bf16 mirror of g_x
__device__ __align__(16) __nv_bfloat16 g_xdbf[BD];   // exact bf16 mirror of g_xd
// W 3-level bf16 split, TRANSPOSED: g_Wt[level][n][k], n,k in [0,256).
__device__ __align__(16) __nv_bfloat16 g_Wt[3 * 256 * 256];

// ---------------------------------------------------------------------------
__device__ __forceinline__ void cpasync16(uint32_t dst, const void* src) {
    asm volatile("cp.async.ca.shared.global [%0], [%1], 16;" :: "r"(dst), "l"(src));
}
__device__ __forceinline__ void ldsm4(uint32_t& r0, uint32_t& r1, uint32_t& r2,
                                      uint32_t& r3, uint32_t addr) {
    asm volatile("ldmatrix.sync.aligned.m8n8.x4.shared.b16 {%0,%1,%2,%3}, [%4];"
                 : "=r"(r0), "=r"(r1), "=r"(r2), "=r"(r3) : "r"(addr));
}

__device__ __forceinline__ float flip_p(float vx, float bv, float ga, float s) {
    float d  = ((vx + bv) * s) * 0.5f;
    float gm = d - (ga * 0.5f) * s;
    float t  = gm - 2.5f;
    return 1.0f / (1.0f + expf(-t));
}

__global__ void kinit(const float* __restrict__ x_in, const float* __restrict__ xa_in) {
    int i = blockIdx.x * blockDim.x + threadIdx.x;
    if (i < BD) {
        float x = x_in[i];
        g_x[i] = x; g_xa[i] = xa_in[i];
        g_xbf[i] = __float2bfloat16(x);          // exact (binary)
    }
}

// W staging: 3-level bf16 Kahan split, stored transposed [level][n][k].
__global__ void kprep(const float* __restrict__ Wm_in) {
    int k = threadIdx.x;
    int n = blockIdx.x;
    float w = Wm_in[k * 256 + n];
    __nv_bfloat16 h = __float2bfloat16(w);
    float r1 = w - __bfloat162float(h);
    __nv_bfloat16 m = __float2bfloat16(r1);
    float r2 = r1 - __bfloat162float(m);
    __nv_bfloat16 l = __float2bfloat16(r2);
    size_t base = (size_t)n * 256 + k;
    g_Wt[base]             = h;
    g_Wt[65536 + base]     = m;
    g_Wt[2 * 65536 + base] = l;
}

// ---------------------------------------------------------------------------
// Tensor-core GEMM via mma.sync + ldmatrix, XOR-swizzled conflict-free smem.
// C[16384,256] = A @ (Wh+Wm+Wl). CTA: M128 x N64, 8 warps (warp = M16 x N64).
// Accumulation order (kt -> level -> nt) bit-identical to R9.
// Smem unit swizzle: 16B unit q of row r stored at r*64 + ((q ^ ((r>>1)&3))*16).
#define KC 32
#define ABUF_BYTES 8192                     // 128 rows x 64B
#define BBUF_BYTES 4096                     // 64 rows x 64B (per level)
#define BUF_BYTES  (ABUF_BYTES + 3 * BBUF_BYTES)
__global__ __launch_bounds__(256) void gemm_tc(const __nv_bfloat16* __restrict__ Abf,
                                               float* __restrict__ C) {
    __shared__ __align__(16) uint8_t smemraw[2][BUF_BYTES];

    const int t    = threadIdx.x;
    const int wid  = t >> 5;
    const int lane = t & 31;
    const int g    = lane >> 2;
    const int tg   = lane & 3;
    const int m0   = blockIdx.x * 128;
    const int n0   = blockIdx.y * 64;

    const uint32_t smem0 = (uint32_t)__cvta_generic_to_shared(&smemraw[0][0]);
    const uint32_t smem1 = (uint32_t)__cvta_generic_to_shared(&smemraw[1][0]);

    float acc[8][4];
    #pragma unroll
    for (int nt = 0; nt < 8; nt++)
        #pragma unroll
        for (int r = 0; r < 4; r++) acc[nt][r] = 0.0f;

    auto ldchunk = [&](int c, int buf) {
        int k0 = c * KC;
        uint32_t base = buf ? smem1 : smem0;
        #pragma unroll
        for (int i = 0; i < 2; i++) {                 // A: 512 x 16B units
            int u = t + 256 * i;
            int m = u >> 2, q = u & 3;
            uint32_t dst = base + m * 64 + ((q ^ ((m >> 1) & 3)) << 4);
            cpasync16(dst, &Abf[(size_t)(m0 + m) * 256 + k0 + q * 8]);
        }
        #pragma unroll
        for (int i = 0; i < 3; i++) {                 // W: 3 x 256 x 16B units
            int u = t + 256 * i;
            int l = u >> 8, rem = u & 255;
            int n = rem >> 2, q = rem & 3;
            uint32_t dst = base + ABUF_BYTES + l * BBUF_BYTES
                         + n * 64 + ((q ^ ((n >> 1) & 3)) << 4);
            cpasync16(dst, &g_Wt[(size_t)l * 65536 + (size_t)(n0 + n) * 256 + k0 + q * 8]);
        }
        asm volatile("cp.async.commit_group;");
    };

    // Per-lane ldmatrix row geometry (constant across chunks).
    const int rL   = lane & 15;           // row within 16-row tile
    const int usel = lane >> 4;           // 16B-unit select (k half)
    const int mA   = wid * 16 + rL;       // A row
    const int sA   = (mA >> 1) & 3;       // A swizzle key
    const int sB   = (rL >> 1) & 3;       // B swizzle key (np*16 doesn't affect it)

    ldchunk(0, 0);

    #pragma unroll 1
    for (int c = 0; c < 256 / KC; c++) {
        if (c + 1 < 256 / KC) {
            ldchunk(c + 1, (c + 1) & 1);
            asm volatile("cp.async.wait_group 1;");
        } else {
            asm volatile("cp.async.wait_group 0;");
        }
        __syncthreads();

        const uint32_t base = (c & 1) ? smem1 : smem0;
        const uint32_t arow = base + mA * 64;

        #pragma unroll
        for (int kt = 0; kt < 2; kt++) {
            const int ku = (kt << 1) | usel;
            uint32_t a0, a1, a2, a3;
            ldsm4(a0, a1, a2, a3, arow + ((ku ^ sA) << 4));
            #pragma unroll
            for (int l = 0; l < 3; l++) {
                const uint32_t bbase = base + ABUF_BYTES + l * BBUF_BYTES
                                     + ((ku ^ sB) << 4);
                #pragma unroll
                for (int np = 0; np < 4; np++) {
                    uint32_t b0, b1, b2, b3;
                    ldsm4(b0, b1, b2, b3, bbase + (np * 16 + rL) * 64);
                    asm volatile(
                        "mma.sync.aligned.m16n8k16.row.col.f32.bf16.bf16.f32 "
                        "{%0,%1,%2,%3}, {%4,%5,%6,%7}, {%8,%9}, {%0,%1,%2,%3};"
                        : "+f"(acc[2*np][0]), "+f"(acc[2*np][1]),
                          "+f"(acc[2*np][2]), "+f"(acc[2*np][3])
                        : "r"(a0), "r"(a1), "r"(a2), "r"(a3), "r"(b0), "r"(b2));
                    asm volatile(
                        "mma.sync.aligned.m16n8k16.row.col.f32.bf16.bf16.f32 "
                        "{%0,%1,%2,%3}, {%4,%5,%6,%7}, {%8,%9}, {%0,%1,%2,%3};"
                        : "+f"(acc[2*np+1][0]), "+f"(acc[2*np+1][1]),
                          "+f"(acc[2*np+1][2]), "+f"(acc[2*np+1][3])
                        : "r"(a0), "r"(a1), "r"(a2), "r"(a3), "r"(b1), "r"(b3));
                }
            }
        }
        __syncthreads();
    }

    // Epilogue: c0,c1 -> row g, cols 2tg,2tg+1; c2,c3 -> row g+8.
    #pragma unroll
    for (int nt = 0; nt < 8; nt++) {
        size_t row = (size_t)(m0 + wid * 16 + g);
        int    col = n0 + nt * 8 + tg * 2;
        *(float2*)&C[row * 256 + col]       = make_float2(acc[nt][0], acc[nt][1]);
        *(float2*)&C[(row + 8) * 256 + col] = make_float2(acc[nt][2], acc[nt][3]);
    }
}

// ---------------------------------------------------------------------------
__global__ void phase1(const float* __restrict__ rr_s, const float* __restrict__ bvec) {
    int i = blockIdx.x * blockDim.x + threadIdx.x;
    if (i >= BD) return;
    float x  = g_x[i];
    float s  = 1.0f - 2.0f * x;
    float ga = (x - g_xa[i]) / 1.0e4f;
    float p  = flip_p(g_vx[i], bvec[i & 255], ga, s);
    float ind = (rr_s[i] < p) ? 1.0f : 0.0f;
    float xd = x + ind * s;
    g_xd[i]   = xd;
    g_xdbf[i] = __float2bfloat16(xd);
    g_p[i]    = p;
}

__device__ __forceinline__ double wsumd(double v) {
    #pragma unroll
    for (int off = 16; off; off >>= 1) v += __shfl_xor_sync(0xffffffffu, v, off, 32);
    return v;
}

__global__ __launch_bounds__(256) void phase2(const float* __restrict__ noise_s,
                                              const float* __restrict__ u_s,
                                              const float* __restrict__ rr_next,
                                              const float* __restrict__ bvec,
                                              float* __restrict__ out, int last) {
    int gwarp = (blockIdx.x * blockDim.x + threadIdx.x) >> 5;
    int lane  = threadIdx.x & 31;
    if (gwarp >= B_) return;
    size_t base  = (size_t)gwarp * 256 + lane * 8;
    int    dbase = lane * 8;

    float xv[8], xav[8], vxv[8], vxdv[8], xdv[8], pv[8], nzv[8], bvv[8];
    #pragma unroll
    for (int h = 0; h < 2; h++) {
        *(float4*)&xv  [4*h] = __ldg((const float4*)&g_x  [base + 4*h]);
        *(float4*)&xav [4*h] = __ldg((const float4*)&g_xa [base + 4*h]);
        *(float4*)&vxv [4*h] = __ldg((const float4*)&g_vx [base + 4*h]);
        *(float4*)&vxdv[4*h] = __ldg((const float4*)&g_vxd[base + 4*h]);
        *(float4*)&xdv [4*h] = __ldg((const float4*)&g_xd [base + 4*h]);
        *(float4*)&pv  [4*h] = __ldg((const float4*)&g_p  [base + 4*h]);
        *(float4*)&nzv [4*h] = __ldg((const float4*)&noise_s[base + 4*h]);
        *(float4*)&bvv [4*h] = __ldg((const float4*)&bvec [dbase + 4*h]);
    }

    float xdav[8], p2v[8];
    double q = 0.0;

    #pragma unroll
    for (int j = 0; j < 8; j++) {
        float x = xv[j], xa = xav[j], vx = vxv[j], vxd = vxdv[j];
        float xd = xdv[j], p = pv[j], nz = nzv[j], bv = bvv[j];

        float ga  = (x - xa) / 1.0e4f;
        float ind = (x != xd) ? 1.0f : 0.0f;
        float xda = (xa + 0.25f * ga) + 0.70710678118654752f * nz;

        float s2  = 1.0f - 2.0f * xd;
        float ga2 = (xd - xda) / 1.0e4f;
        float p2  = flip_p(vxd, bv, ga2, s2);

        float a1 = (ind != 0.0f) ? (p  + 1e-10f) : ((1.0f - p)  + 1e-10f);
        float a2 = (ind != 0.0f) ? (p2 + 1e-10f) : ((1.0f - p2) + 1e-10f);
        float t_log = __logf(a2) - __logf(a1);

        float dc = x  - xa;
        float dn = xd - xda;
        float t_m = ((0.5f * (vxd * xd) + bv * xd) - (dn * dn) * 5e-5f)
                  - ((0.5f * (vx  * x ) + bv * x ) - (dc * dc) * 5e-5f);

        float ff = xda - (xa + 0.25f * ga);
        float fr = xa  - (xda + 0.25f * ga2);
        float t_q = ff * ff - fr * fr;

        q += (double)(t_log + t_m + t_q);

        xdav[j] = xda; p2v[j] = p2;
    }

    double la = wsumd(q);
    int accept = la > log((double)__ldg(&u_s[gwarp]));

    if (last) {
        float o1[8], o2[8];
        #pragma unroll
        for (int j = 0; j < 8; j++) {
            o1[j] = accept ? xdv[j]  : xv[j];
            o2[j] = accept ? xdav[j] : xav[j];
        }
        #pragma unroll
        for (int h = 0; h < 2; h++) {
            *(float4*)&out[base + 4*h]      = *(float4*)&o1[4*h];
            *(float4*)&out[BD + base + 4*h] = *(float4*)&o2[4*h];
        }
        return;
    }

    if (accept) {
        #pragma unroll
        for (int h = 0; h < 2; h++) {
            *(float4*)&g_x [base + 4*h] = *(float4*)&xdv [4*h];
            *(float4*)&g_xa[base + 4*h] = *(float4*)&xdav[4*h];
            *(float4*)&g_vx[base + 4*h] = *(float4*)&vxdv[4*h];
            *(float4*)&g_p [base + 4*h] = *(float4*)&p2v [4*h];
        }
    }

    // Next proposal: p_next = accept ? p2 : p (bit-identical to recompute).
    float rrv[8], xdn[8];
    __nv_bfloat16 xdb[8];
    #pragma unroll
    for (int h = 0; h < 2; h++)
        *(float4*)&rrv[4*h] = __ldg((const float4*)&rr_next[base + 4*h]);
    #pragma unroll
    for (int j = 0; j < 8; j++) {
        float xn = accept ? xdv[j] : xv[j];
        float pn = accept ? p2v[j] : pv[j];
        float s  = 1.0f - 2.0f * xn;
        float ind = (rrv[j] < pn) ? 1.0f : 0.0f;
        xdn[j] = xn + ind * s;
        xdb[j] = __float2bfloat16(xdn[j]);
    }
    #pragma unroll
    for (int h = 0; h < 2; h++)
        *(float4*)&g_xd[base + 4*h] = *(float4*)&xdn[4*h];
    *(uint4*)&g_xdbf[base] = *(uint4*)&xdb[0];
}

// ---------------------------------------------------------------------------
extern "C" void kernel_launch(void* const* d_in, const int* in_sizes, int n_in,
                              void* d_out, int out_size) {
    (void)in_sizes; (void)n_in; (void)out_size;
    const float* x_in  = (const float*)d_in[0];
    const float* xa_in = (const float*)d_in[1];
    const float* Wm    = (const float*)d_in[2];
    const float* bvec  = (const float*)d_in[3];
    const float* rr    = (const float*)d_in[4];
    const float* noise = (const float*)d_in[5];
    const float* u     = (const float*)d_in[6];
    float* out = (float*)d_out;

    __nv_bfloat16* xbf_p;  cudaGetSymbolAddress((void**)&xbf_p,  g_xbf);
    __nv_bfloat16* xdbf_p; cudaGetSymbolAddress((void**)&xdbf_p, g_xdbf);
    float* vx_p;  cudaGetSymbolAddress((void**)&vx_p,  g_vx);
    float* vxd_p; cudaGetSymbolAddress((void**)&vxd_p, g_vxd);

    dim3 ggrid(B_ / 128, 256 / 64);

    kinit<<<BD / 256, 256>>>(x_in, xa_in);
    kprep<<<256, 256>>>(Wm);
    gemm_tc<<<ggrid, 256>>>(xbf_p, vx_p);                // g_vx = x @ W
    phase1<<<BD / 256, 256>>>(rr, bvec);                 // proposal for step 0
    for (int s = 0; s < NSTEPS_; s++) {
        gemm_tc<<<ggrid, 256>>>(xdbf_p, vxd_p);          // g_vxd = x_delta @ W
        int lastf = (s == NSTEPS_ - 1);
        phase2<<<B_ / 8, 256>>>(noise + (size_t)s * BD, u + (size_t)s * B_,
                                lastf ? (const float*)d_in[4]
                                      : rr + (size_t)(s + 1) * BD,
                                bvec, out, lastf);
    }
}

// round 11
// speedup vs baseline: 1.4788x; 1.0317x over previous
#include <cuda_runtime.h>
#include <cuda_bf16.h>
#include <cstdint>

#define B_      16384
#define D_      256
#define NSTEPS_ 5
#define BD      (B_*D_)

// ---------------------------------------------------------------------------
// Persistent state (re-initialized on every kernel_launch -> deterministic).
// Binary state lives ONLY in bf16 (exact for {0,1}).
__device__ __align__(16) float g_xa [BD];
__device__ __align__(16) float g_vx [BD];
__device__ __align__(16) float g_vxd[BD];
__device__ __align__(16) float g_p  [BD];
__device__ __align__(16) __nv_bfloat16 g_xbf [BD];   // current binary state
__device__ __align__(16) __nv_bfloat16 g_xdbf[BD];   // proposal x_delta
// W 3-level bf16 split, TRANSPOSED: g_Wt[level][n][k], n,k in [0,256).
__device__ __align__(16) __nv_bfloat16 g_Wt[3 * 256 * 256];

// ---------------------------------------------------------------------------
__device__ __forceinline__ void cpasync16(uint32_t dst, const void* src) {
    asm volatile("cp.async.ca.shared.global [%0], [%1], 16;" :: "r"(dst), "l"(src));
}
__device__ __forceinline__ void ldsm4(uint32_t& r0, uint32_t& r1, uint32_t& r2,
                                      uint32_t& r3, uint32_t addr) {
    asm volatile("ldmatrix.sync.aligned.m8n8.x4.shared.b16 {%0,%1,%2,%3}, [%4];"
                 : "=r"(r0), "=r"(r1), "=r"(r2), "=r"(r3) : "r"(addr));
}

// flip probability: decision-critical, bit-identical to all passing rounds.
__device__ __forceinline__ float flip_p(float vx, float bv, float ga, float s) {
    float d  = ((vx + bv) * s) * 0.5f;
    float gm = d - (ga * 0.5f) * s;
    float t  = gm - 2.5f;
    return 1.0f / (1.0f + expf(-t));
}

// Division-free polynomial log (feeds la only; abs err <~2e-6 at extremes).
__device__ __forceinline__ float fast_log(float a) {
    int ix = __float_as_int(a);
    int e  = (ix - 0x3f3504f3) & 0xff800000;       // center mantissa at sqrt(0.5)
    float m  = __int_as_float(ix - e);             // m in [0.7071, 1.4142)
    float kf = (float)(e >> 23);
    float f  = m - 1.0f;                           // f in [-0.293, 0.414]
    float r  = 0.09090909f;                        // Taylor log1p, degree 11
    r = fmaf(r, f, -0.1f);
    r = fmaf(r, f,  0.11111111f);
    r = fmaf(r, f, -0.125f);
    r = fmaf(r, f,  0.14285714f);
    r = fmaf(r, f, -0.16666667f);
    r = fmaf(r, f,  0.2f);
    r = fmaf(r, f, -0.25f);
    r = fmaf(r, f,  0.33333333f);
    r = fmaf(r, f, -0.5f);
    r = fmaf(r, f,  1.0f);
    return fmaf(kf, 0.6931472f, r * f);
}

__global__ void kinit(const float* __restrict__ x_in, const float* __restrict__ xa_in) {
    int i4 = (blockIdx.x * blockDim.x + threadIdx.x) * 4;
    if (i4 >= BD) return;
    float4 x = *(const float4*)&x_in[i4];
    *(float4*)&g_xa[i4] = *(const float4*)&xa_in[i4];
    __nv_bfloat16 xb[4] = { __float2bfloat16(x.x), __float2bfloat16(x.y),
                            __float2bfloat16(x.z), __float2bfloat16(x.w) };
    *(uint2*)&g_xbf[i4] = *(uint2*)xb;
}

// W staging: 3-level bf16 Kahan split, stored transposed [level][n][k].
__global__ void kprep(const float* __restrict__ Wm_in) {
    int k = threadIdx.x;
    int n = blockIdx.x;
    float w = Wm_in[k * 256 + n];
    __nv_bfloat16 h = __float2bfloat16(w);
    float r1 = w - __bfloat162float(h);
    __nv_bfloat16 m = __float2bfloat16(r1);
    float r2 = r1 - __bfloat162float(m);
    __nv_bfloat16 l = __float2bfloat16(r2);
    size_t base = (size_t)n * 256 + k;
    g_Wt[base]             = h;
    g_Wt[65536 + base]     = m;
    g_Wt[2 * 65536 + base] = l;
}

// ---------------------------------------------------------------------------
// Tensor-core GEMM (identical to R10): mma.sync + ldmatrix, XOR-swizzled smem.
#define KC 32
#define ABUF_BYTES 8192
#define BBUF_BYTES 4096
#define BUF_BYTES  (ABUF_BYTES + 3 * BBUF_BYTES)
__global__ __launch_bounds__(256) void gemm_tc(const __nv_bfloat16* __restrict__ Abf,
                                               float* __restrict__ C) {
    __shared__ __align__(16) uint8_t smemraw[2][BUF_BYTES];

    const int t    = threadIdx.x;
    const int wid  = t >> 5;
    const int lane = t & 31;
    const int g    = lane >> 2;
    const int tg   = lane & 3;
    const int m0   = blockIdx.x * 128;
    const int n0   = blockIdx.y * 64;

    const uint32_t smem0 = (uint32_t)__cvta_generic_to_shared(&smemraw[0][0]);
    const uint32_t smem1 = (uint32_t)__cvta_generic_to_shared(&smemraw[1][0]);

    float acc[8][4];
    #pragma unroll
    for (int nt = 0; nt < 8; nt++)
        #pragma unroll
        for (int r = 0; r < 4; r++) acc[nt][r] = 0.0f;

    auto ldchunk = [&](int c, int buf) {
        int k0 = c * KC;
        uint32_t base = buf ? smem1 : smem0;
        #pragma unroll
        for (int i = 0; i < 2; i++) {
            int u = t + 256 * i;
            int m = u >> 2, q = u & 3;
            uint32_t dst = base + m * 64 + ((q ^ ((m >> 1) & 3)) << 4);
            cpasync16(dst, &Abf[(size_t)(m0 + m) * 256 + k0 + q * 8]);
        }
        #pragma unroll
        for (int i = 0; i < 3; i++) {
            int u = t + 256 * i;
            int l = u >> 8, rem = u & 255;
            int n = rem >> 2, q = rem & 3;
            uint32_t dst = base + ABUF_BYTES + l * BBUF_BYTES
                         + n * 64 + ((q ^ ((n >> 1) & 3)) << 4);
            cpasync16(dst, &g_Wt[(size_t)l * 65536 + (size_t)(n0 + n) * 256 + k0 + q * 8]);
        }
        asm volatile("cp.async.commit_group;");
    };

    const int rL   = lane & 15;
    const int usel = lane >> 4;
    const int mA   = wid * 16 + rL;
    const int sA   = (mA >> 1) & 3;
    const int sB   = (rL >> 1) & 3;

    ldchunk(0, 0);

    #pragma unroll 1
    for (int c = 0; c < 256 / KC; c++) {
        if (c + 1 < 256 / KC) {
            ldchunk(c + 1, (c + 1) & 1);
            asm volatile("cp.async.wait_group 1;");
        } else {
            asm volatile("cp.async.wait_group 0;");
        }
        __syncthreads();

        const uint32_t base = (c & 1) ? smem1 : smem0;
        const uint32_t arow = base + mA * 64;

        #pragma unroll
        for (int kt = 0; kt < 2; kt++) {
            const int ku = (kt << 1) | usel;
            uint32_t a0, a1, a2, a3;
            ldsm4(a0, a1, a2, a3, arow + ((ku ^ sA) << 4));
            #pragma unroll
            for (int l = 0; l < 3; l++) {
                const uint32_t bbase = base + ABUF_BYTES + l * BBUF_BYTES
                                     + ((ku ^ sB) << 4);
                #pragma unroll
                for (int np = 0; np < 4; np++) {
                    uint32_t b0, b1, b2, b3;
                    ldsm4(b0, b1, b2, b3, bbase + (np * 16 + rL) * 64);
                    asm volatile(
                        "mma.sync.aligned.m16n8k16.row.col.f32.bf16.bf16.f32 "
                        "{%0,%1,%2,%3}, {%4,%5,%6,%7}, {%8,%9}, {%0,%1,%2,%3};"
                        : "+f"(acc[2*np][0]), "+f"(acc[2*np][1]),
                          "+f"(acc[2*np][2]), "+f"(acc[2*np][3])
                        : "r"(a0), "r"(a1), "r"(a2), "r"(a3), "r"(b0), "r"(b2));
                    asm volatile(
                        "mma.sync.aligned.m16n8k16.row.col.f32.bf16.bf16.f32 "
                        "{%0,%1,%2,%3}, {%4,%5,%6,%7}, {%8,%9}, {%0,%1,%2,%3};"
                        : "+f"(acc[2*np+1][0]), "+f"(acc[2*np+1][1]),
                          "+f"(acc[2*np+1][2]), "+f"(acc[2*np+1][3])
                        : "r"(a0), "r"(a1), "r"(a2), "r"(a3), "r"(b1), "r"(b3));
                }
            }
        }
        __syncthreads();
    }

    #pragma unroll
    for (int nt = 0; nt < 8; nt++) {
        size_t row = (size_t)(m0 + wid * 16 + g);
        int    col = n0 + nt * 8 + tg * 2;
        *(float2*)&C[row * 256 + col]       = make_float2(acc[nt][0], acc[nt][1]);
        *(float2*)&C[(row + 8) * 256 + col] = make_float2(acc[nt][2], acc[nt][3]);
    }
}

// ---------------------------------------------------------------------------
__global__ void phase1(const float* __restrict__ rr_s, const float* __restrict__ bvec) {
    int i = blockIdx.x * blockDim.x + threadIdx.x;
    if (i >= BD) return;
    float x  = __bfloat162float(g_xbf[i]);         // exact
    float s  = 1.0f - 2.0f * x;
    float ga = (x - g_xa[i]) / 1.0e4f;
    float p  = flip_p(g_vx[i], bvec[i & 255], ga, s);
    float ind = (rr_s[i] < p) ? 1.0f : 0.0f;
    float xd = x + ind * s;
    g_xdbf[i] = __float2bfloat16(xd);              // exact
    g_p[i]    = p;
}

__device__ __forceinline__ double wsumd(double v) {
    #pragma unroll
    for (int off = 16; off; off >>= 1) v += __shfl_xor_sync(0xffffffffu, v, off, 32);
    return v;
}

// Phase 2 (fused next proposal): one warp per row, lane owns 8 contiguous
// elements. Binary state flows in/out as bf16 (exact). Logs via fast_log
// (FMA pipe). p2 path (expf+div) bit-identical; p_next = accept?p2:p.
__global__ __launch_bounds__(256) void phase2(const float* __restrict__ noise_s,
                                              const float* __restrict__ u_s,
                                              const float* __restrict__ rr_next,
                                              const float* __restrict__ bvec,
                                              float* __restrict__ out, int last) {
    int gwarp = (blockIdx.x * blockDim.x + threadIdx.x) >> 5;
    int lane  = threadIdx.x & 31;
    if (gwarp >= B_) return;
    size_t base  = (size_t)gwarp * 256 + lane * 8;
    int    dbase = lane * 8;

    __nv_bfloat16 xb[8], xdb[8];
    *(uint4*)xb  = *(const uint4*)&g_xbf [base];
    *(uint4*)xdb = *(const uint4*)&g_xdbf[base];

    float xav[8], vxv[8], vxdv[8], pv[8], nzv[8], bvv[8];
    #pragma unroll
    for (int h = 0; h < 2; h++) {
        *(float4*)&xav [4*h] = __ldg((const float4*)&g_xa [base + 4*h]);
        *(float4*)&vxv [4*h] = __ldg((const float4*)&g_vx [base + 4*h]);
        *(float4*)&vxdv[4*h] = __ldg((const float4*)&g_vxd[base + 4*h]);
        *(float4*)&pv  [4*h] = __ldg((const float4*)&g_p  [base + 4*h]);
        *(float4*)&nzv [4*h] = __ldg((const float4*)&noise_s[base + 4*h]);
        *(float4*)&bvv [4*h] = __ldg((const float4*)&bvec [dbase + 4*h]);
    }

    float xv[8], xdv[8], xdav[8], p2v[8];
    double q = 0.0;

    #pragma unroll
    for (int j = 0; j < 8; j++) {
        float x  = __bfloat162float(xb[j]);        // exact
        float xd = __bfloat162float(xdb[j]);       // exact
        float xa = xav[j], vx = vxv[j], vxd = vxdv[j];
        float p = pv[j], nz = nzv[j], bv = bvv[j];

        float ga  = (x - xa) / 1.0e4f;
        float ind = (x != xd) ? 1.0f : 0.0f;
        float xda = (xa + 0.25f * ga) + 0.70710678118654752f * nz;

        float s2  = 1.0f - 2.0f * xd;
        float ga2 = (xd - xda) / 1.0e4f;
        float p2  = flip_p(vxd, bv, ga2, s2);

        float a1 = (ind != 0.0f) ? (p  + 1e-10f) : ((1.0f - p)  + 1e-10f);
        float a2 = (ind != 0.0f) ? (p2 + 1e-10f) : ((1.0f - p2) + 1e-10f);
        float t_log = fast_log(a2) - fast_log(a1);

        float dc = x  - xa;
        float dn = xd - xda;
        float t_m = ((0.5f * (vxd * xd) + bv * xd) - (dn * dn) * 5e-5f)
                  - ((0.5f * (vx  * x ) + bv * x ) - (dc * dc) * 5e-5f);

        float ff = xda - (xa + 0.25f * ga);
        float fr = xa  - (xda + 0.25f * ga2);
        float t_q = ff * ff - fr * fr;

        q += (double)(t_log + t_m + t_q);

        xv[j] = x; xdv[j] = xd; xdav[j] = xda; p2v[j] = p2;
    }

    double la = wsumd(q);
    int accept = la > log((double)__ldg(&u_s[gwarp]));

    if (last) {
        float o1[8], o2[8];
        #pragma unroll
        for (int j = 0; j < 8; j++) {
            o1[j] = accept ? xdv[j]  : xv[j];
            o2[j] = accept ? xdav[j] : xav[j];
        }
        #pragma unroll
        for (int h = 0; h < 2; h++) {
            *(float4*)&out[base + 4*h]      = *(float4*)&o1[4*h];
            *(float4*)&out[BD + base + 4*h] = *(float4*)&o2[4*h];
        }
        return;
    }

    if (accept) {
        *(uint4*)&g_xbf[base] = *(uint4*)xdb;      // xd becomes x (exact bf16)
        #pragma unroll
        for (int h = 0; h < 2; h++) {
            *(float4*)&g_xa[base + 4*h] = *(float4*)&xdav[4*h];
            *(float4*)&g_vx[base + 4*h] = *(float4*)&vxdv[4*h];
            *(float4*)&g_p [base + 4*h] = *(float4*)&p2v [4*h];
        }
    }

    // Next proposal: p_next = accept ? p2 : p (bit-identical to recompute).
    float rrv[8];
    __nv_bfloat16 xdn[8];
    #pragma unroll
    for (int h = 0; h < 2; h++)
        *(float4*)&rrv[4*h] = __ldg((const float4*)&rr_next[base + 4*h]);
    #pragma unroll
    for (int j = 0; j < 8; j++) {
        float xn = accept ? xdv[j] : xv[j];
        float pn = accept ? p2v[j] : pv[j];
        float s  = 1.0f - 2.0f * xn;
        float ind = (rrv[j] < pn) ? 1.0f : 0.0f;
        xdn[j] = __float2bfloat16(xn + ind * s);   // exact
    }
    *(uint4*)&g_xdbf[base] = *(uint4*)xdn;
}

// ---------------------------------------------------------------------------
extern "C" void kernel_launch(void* const* d_in, const int* in_sizes, int n_in,
                              void* d_out, int out_size) {
    (void)in_sizes; (void)n_in; (void)out_size;
    const float* x_in  = (const float*)d_in[0];
    const float* xa_in = (const float*)d_in[1];
    const float* Wm    = (const float*)d_in[2];
    const float* bvec  = (const float*)d_in[3];
    const float* rr    = (const float*)d_in[4];
    const float* noise = (const float*)d_in[5];
    const float* u     = (const float*)d_in[6];
    float* out = (float*)d_out;

    __nv_bfloat16* xbf_p;  cudaGetSymbolAddress((void**)&xbf_p,  g_xbf);
    __nv_bfloat16* xdbf_p; cudaGetSymbolAddress((void**)&xdbf_p, g_xdbf);
    float* vx_p;  cudaGetSymbolAddress((void**)&vx_p,  g_vx);
    float* vxd_p; cudaGetSymbolAddress((void**)&vxd_p, g_vxd);

    dim3 ggrid(B_ / 128, 256 / 64);

    kinit<<<BD / 1024, 256>>>(x_in, xa_in);
    kprep<<<256, 256>>>(Wm);
    gemm_tc<<<ggrid, 256>>>(xbf_p, vx_p);                // g_vx = x @ W
    phase1<<<BD / 256, 256>>>(rr, bvec);                 // proposal for step 0
    for (int s = 0; s < NSTEPS_; s++) {
        gemm_tc<<<ggrid, 256>>>(xdbf_p, vxd_p);          // g_vxd = x_delta @ W
        int lastf = (s == NSTEPS_ - 1);
        phase2<<<B_ / 8, 256>>>(noise + (size_t)s * BD, u + (size_t)s * B_,
                                lastf ? (const float*)d_in[4]
                                      : rr + (size_t)(s + 1) * BD,
                                bvec, out, lastf);
    }
}